// round 2
// baseline (speedup 1.0000x reference)
#include <cuda_runtime.h>

// ============================================================================
// Intergrator_5952824672851  (CFD cell integrator, F=6M faces, C=4M cells)
//
// per cell c, faces f0,f1,f2 = cell_face[:,c], normals n_i = unv[c,i,:]:
//   dot_i = uv[fi] . n_i
//   loss_continuity[c] = sum_i dot_i * area[fi]
//   A = sum_i uv[fi] * (dot_i * area[fi])          (einsum simplification)
//   P = sum_i p[fi] * n_i * area[fi]
//   D = sum_i flux_D[fi]
//   out[c] = rhs_coef[c] * (-A - P/rho[c]) + D
//
// Strategy: pack per-face data into one 32B-aligned record so each random
// gather costs exactly one L2 sector instead of four.
// cell_face element width is sniffed at runtime (int64 / int32 / float32)
// and all indices are clamped so the kernel can never fault.
// ============================================================================

#define MAX_F 6000000

// 2 float4 per face: [u, v, p, area], [fDx, fDy, 0, 0]  -> 32B record
__device__ float4 g_pack[2 * MAX_F];
__device__ int    g_idx_kind;   // 0 = int64, 1 = int32, 2 = float32

__global__ void detect_idx_kind_kernel(const unsigned int* __restrict__ w,
                                       long long nwords) {
    if (blockIdx.x != 0 || threadIdx.x != 0) return;
    bool odd_all_zero = true;   // int64 little-endian: high word of each elem == 0
    bool all_small    = true;   // int32 indices < 2^24
    long long stride = nwords / 128;
    if (stride < 2) stride = 2;
    for (int i = 0; i < 128; i++) {
        long long pos = stride * i;
        if (pos + 1 >= nwords) break;
        unsigned int lo = w[pos & ~1LL];
        unsigned int hi = w[pos | 1LL];
        if (hi != 0u) odd_all_zero = false;
        if (lo >= (1u << 24) || (hi >= (1u << 24) && hi != 0u)) all_small = false;
    }
    g_idx_kind = odd_all_zero ? 0 : (all_small ? 1 : 2);
}

__global__ void pack_faces_kernel(const float2* __restrict__ uv_face,
                                  const float*  __restrict__ p_face,
                                  const float2* __restrict__ flux_D,
                                  const float*  __restrict__ face_area,
                                  int F) {
    int f = blockIdx.x * blockDim.x + threadIdx.x;
    if (f >= F) return;
    float2 uv = uv_face[f];
    float2 fd = flux_D[f];
    float  p  = p_face[f];
    float  a  = face_area[f];
    g_pack[2 * f + 0] = make_float4(uv.x, uv.y, p, a);
    g_pack[2 * f + 1] = make_float4(fd.x, fd.y, 0.0f, 0.0f);
}

__device__ __forceinline__ long long load_idx(const void* p, int kind, long long i) {
    if (kind == 0) return ((const long long*)p)[i];
    if (kind == 1) return (long long)(((const int*)p)[i]);
    return (long long)(((const float*)p)[i]);
}

__device__ __forceinline__ long long clampF(long long v, long long F) {
    if (v < 0) v = 0;
    if (v >= F) v = F - 1;
    return v;
}

__global__ void cell_integrate_kernel(const void*   __restrict__ cell_face, // [3, C]
                                      const float2* __restrict__ unv,       // [C,3,2]
                                      const float*  __restrict__ rho,       // [C]
                                      const float*  __restrict__ rhs_coef,  // [C]
                                      float*        __restrict__ out,       // [3C]
                                      int C, int F) {
    int c = blockIdx.x * blockDim.x + threadIdx.x;
    if (c >= C) return;

    int kind = g_idx_kind;  // uniform across grid, L1/L2 cached

    long long cf0 = clampF(load_idx(cell_face, kind, c), F);
    long long cf1 = clampF(load_idx(cell_face, kind, (long long)C + c), F);
    long long cf2 = clampF(load_idx(cell_face, kind, 2LL * C + c), F);

    float2 n0 = unv[3 * c + 0];
    float2 n1 = unv[3 * c + 1];
    float2 n2 = unv[3 * c + 2];

    // Issue all 6 gathers up-front (independent -> MLP)
    float4 a0 = g_pack[2 * cf0 + 0];
    float4 b0 = g_pack[2 * cf0 + 1];
    float4 a1 = g_pack[2 * cf1 + 0];
    float4 b1 = g_pack[2 * cf1 + 1];
    float4 a2 = g_pack[2 * cf2 + 0];
    float4 b2 = g_pack[2 * cf2 + 1];

    float dot0 = a0.x * n0.x + a0.y * n0.y;
    float de0  = dot0 * a0.w;
    float pe0  = a0.z * a0.w;
    float dot1 = a1.x * n1.x + a1.y * n1.y;
    float de1  = dot1 * a1.w;
    float pe1  = a1.z * a1.w;
    float dot2 = a2.x * n2.x + a2.y * n2.y;
    float de2  = dot2 * a2.w;
    float pe2  = a2.z * a2.w;

    float loss = de0 + de1 + de2;

    float Ax = a0.x * de0 + a1.x * de1 + a2.x * de2;
    float Ay = a0.y * de0 + a1.y * de1 + a2.y * de2;

    float Px = pe0 * n0.x + pe1 * n1.x + pe2 * n2.x;
    float Py = pe0 * n0.y + pe1 * n1.y + pe2 * n2.y;

    float Dx = b0.x + b1.x + b2.x;
    float Dy = b0.y + b1.y + b2.y;

    float inv_rho = 1.0f / rho[c];
    float rc = rhs_coef[c];

    float ox = rc * (-Ax - inv_rho * Px) + Dx;
    float oy = rc * (-Ay - inv_rho * Py) + Dy;

    out[c] = loss;                                // loss_continuity [C,1]
    float2* o2 = reinterpret_cast<float2*>(out + C);
    o2[c] = make_float2(ox, oy);                  // out [C,2]
}

extern "C" void kernel_launch(void* const* d_in, const int* in_sizes, int n_in,
                              void* d_out, int out_size) {
    // metadata order (reference signature order):
    // 0 uv_face [F,2] f32 | 1 p_face [F,1] f32 | 2 flux_D [F,2] f32
    // 3 unv [C,3,2] f32   | 4 rho [C,1] f32    | 5 rhs_coef [C,1] f32
    // 6 face_area [F,1] f32 | 7 cell_face [3,C] (int64 or downcast)
    const float2* uv_face   = (const float2*)d_in[0];
    const float*  p_face    = (const float*) d_in[1];
    const float2* flux_D    = (const float2*)d_in[2];
    const float2* unv       = (const float2*)d_in[3];
    const float*  rho       = (const float*) d_in[4];
    const float*  rhs_coef  = (const float*) d_in[5];
    const float*  face_area = (const float*) d_in[6];
    const void*   cell_face = d_in[7];

    int F = in_sizes[1];   // p_face element count
    int C = in_sizes[4];   // rho element count
    float* out = (float*)d_out;

    // cell_face element count = 3C regardless of width; probe raw 32-bit words.
    // Assume at least 3C words exist (true for int32/float32; int64 has 6C).
    long long nwords = 3LL * C;

    const int TPB = 256;
    detect_idx_kind_kernel<<<1, 32>>>((const unsigned int*)cell_face, nwords);
    pack_faces_kernel<<<(F + TPB - 1) / TPB, TPB>>>(uv_face, p_face, flux_D, face_area, F);
    cell_integrate_kernel<<<(C + TPB - 1) / TPB, TPB>>>(cell_face, unv, rho, rhs_coef,
                                                        out, C, F);
}

// round 3
// speedup vs baseline: 1.2007x; 1.2007x over previous
#include <cuda_runtime.h>

// ============================================================================
// Intergrator_5952824672851  (CFD cell integrator, F=6M faces, C=4M cells)
//
// per cell c, faces f0,f1,f2 = cell_face[:,c], normals n_i = unv[c,i,:]:
//   dot_i = uv[fi] . n_i
//   loss_continuity[c] = sum_i dot_i * area[fi]
//   A = sum_i uv[fi] * (dot_i * area[fi])
//   P = sum_i p[fi] * n_i * area[fi]
//   D = sum_i flux_D[fi]
//   out[c] = rhs_coef[c] * (-A - P/rho[c]) + D
//
// R2 -> R3: detection kernel parallelized (was 59.7us single-thread serial
// DRAM pointer-walk; now one 128-thread block, one DRAM round-trip ~2us).
// ============================================================================

#define MAX_F 6000000

// 2 float4 per face: [u, v, p, area], [fDx, fDy, 0, 0]  -> 32B record
__device__ float4 g_pack[2 * MAX_F];
__device__ int    g_idx_kind;   // 0 = int64, 1 = int32, 2 = float32

__global__ void detect_idx_kind_kernel(const unsigned int* __restrict__ w,
                                       long long nwords) {
    // 128 threads, each probes one sample pair; ballot-reduce.
    int t = threadIdx.x;
    long long stride = nwords / 128;
    if (stride < 2) stride = 2;
    long long pos = stride * (long long)t;

    bool odd_zero = true;   // int64 LE: high word of each element == 0
    bool small    = true;   // int32 indices < 2^24
    if (pos + 1 < nwords) {
        unsigned int lo = w[pos & ~1LL];
        unsigned int hi = w[pos | 1LL];
        odd_zero = (hi == 0u);
        small    = (lo < (1u << 24)) && (hi < (1u << 24) || hi == 0u);
    }
    unsigned all_oz = __ballot_sync(0xFFFFFFFFu, odd_zero);
    unsigned all_sm = __ballot_sync(0xFFFFFFFFu, small);

    __shared__ unsigned s_oz[4], s_sm[4];
    int wid = t >> 5;
    if ((t & 31) == 0) { s_oz[wid] = all_oz; s_sm[wid] = all_sm; }
    __syncthreads();
    if (t == 0) {
        bool oz = (s_oz[0] & s_oz[1] & s_oz[2] & s_oz[3]) == 0xFFFFFFFFu;
        bool sm = (s_sm[0] & s_sm[1] & s_sm[2] & s_sm[3]) == 0xFFFFFFFFu;
        g_idx_kind = oz ? 0 : (sm ? 1 : 2);
    }
}

__global__ void __launch_bounds__(256)
pack_faces_kernel(const float2* __restrict__ uv_face,
                  const float*  __restrict__ p_face,
                  const float2* __restrict__ flux_D,
                  const float*  __restrict__ face_area,
                  int F) {
    int f = blockIdx.x * blockDim.x + threadIdx.x;
    if (f >= F) return;
    float2 uv = uv_face[f];
    float2 fd = flux_D[f];
    float  p  = p_face[f];
    float  a  = face_area[f];
    g_pack[2 * f + 0] = make_float4(uv.x, uv.y, p, a);
    g_pack[2 * f + 1] = make_float4(fd.x, fd.y, 0.0f, 0.0f);
}

__device__ __forceinline__ long long load_idx(const void* p, int kind, long long i) {
    if (kind == 0) return ((const long long*)p)[i];
    if (kind == 1) return (long long)(((const int*)p)[i]);
    return (long long)(((const float*)p)[i]);
}

__device__ __forceinline__ long long clampF(long long v, long long F) {
    if (v < 0) v = 0;
    if (v >= F) v = F - 1;
    return v;
}

__global__ void __launch_bounds__(256)
cell_integrate_kernel(const void*   __restrict__ cell_face, // [3, C]
                      const float2* __restrict__ unv,       // [C,3,2]
                      const float*  __restrict__ rho,       // [C]
                      const float*  __restrict__ rhs_coef,  // [C]
                      float*        __restrict__ out,       // [3C]
                      int C, int F) {
    int c = blockIdx.x * blockDim.x + threadIdx.x;
    if (c >= C) return;

    int kind = g_idx_kind;  // grid-uniform, cached

    long long cf0 = clampF(load_idx(cell_face, kind, c), F);
    long long cf1 = clampF(load_idx(cell_face, kind, (long long)C + c), F);
    long long cf2 = clampF(load_idx(cell_face, kind, 2LL * C + c), F);

    // Issue all 6 gathers up-front (independent -> MLP)
    float4 a0 = g_pack[2 * cf0 + 0];
    float4 b0 = g_pack[2 * cf0 + 1];
    float4 a1 = g_pack[2 * cf1 + 0];
    float4 b1 = g_pack[2 * cf1 + 1];
    float4 a2 = g_pack[2 * cf2 + 0];
    float4 b2 = g_pack[2 * cf2 + 1];

    float2 n0 = unv[3 * c + 0];
    float2 n1 = unv[3 * c + 1];
    float2 n2 = unv[3 * c + 2];

    float dot0 = a0.x * n0.x + a0.y * n0.y;
    float de0  = dot0 * a0.w;
    float pe0  = a0.z * a0.w;
    float dot1 = a1.x * n1.x + a1.y * n1.y;
    float de1  = dot1 * a1.w;
    float pe1  = a1.z * a1.w;
    float dot2 = a2.x * n2.x + a2.y * n2.y;
    float de2  = dot2 * a2.w;
    float pe2  = a2.z * a2.w;

    float loss = de0 + de1 + de2;

    float Ax = a0.x * de0 + a1.x * de1 + a2.x * de2;
    float Ay = a0.y * de0 + a1.y * de1 + a2.y * de2;

    float Px = pe0 * n0.x + pe1 * n1.x + pe2 * n2.x;
    float Py = pe0 * n0.y + pe1 * n1.y + pe2 * n2.y;

    float Dx = b0.x + b1.x + b2.x;
    float Dy = b0.y + b1.y + b2.y;

    float inv_rho = 1.0f / rho[c];
    float rc = rhs_coef[c];

    float ox = rc * (-Ax - inv_rho * Px) + Dx;
    float oy = rc * (-Ay - inv_rho * Py) + Dy;

    out[c] = loss;                                // loss_continuity [C,1]
    float2* o2 = reinterpret_cast<float2*>(out + C);
    o2[c] = make_float2(ox, oy);                  // out [C,2]
}

extern "C" void kernel_launch(void* const* d_in, const int* in_sizes, int n_in,
                              void* d_out, int out_size) {
    // 0 uv_face [F,2] f32 | 1 p_face [F,1] f32 | 2 flux_D [F,2] f32
    // 3 unv [C,3,2] f32   | 4 rho [C,1] f32    | 5 rhs_coef [C,1] f32
    // 6 face_area [F,1] f32 | 7 cell_face [3,C] (int64 or downcast)
    const float2* uv_face   = (const float2*)d_in[0];
    const float*  p_face    = (const float*) d_in[1];
    const float2* flux_D    = (const float2*)d_in[2];
    const float2* unv       = (const float2*)d_in[3];
    const float*  rho       = (const float*) d_in[4];
    const float*  rhs_coef  = (const float*) d_in[5];
    const float*  face_area = (const float*) d_in[6];
    const void*   cell_face = d_in[7];

    int F = in_sizes[1];   // p_face element count
    int C = in_sizes[4];   // rho element count
    float* out = (float*)d_out;

    long long nwords = 3LL * C;  // safe lower bound on 32-bit word count

    const int TPB = 256;
    detect_idx_kind_kernel<<<1, 128>>>((const unsigned int*)cell_face, nwords);
    pack_faces_kernel<<<(F + TPB - 1) / TPB, TPB>>>(uv_face, p_face, flux_D, face_area, F);
    cell_integrate_kernel<<<(C + TPB - 1) / TPB, TPB>>>(cell_face, unv, rho, rhs_coef,
                                                        out, C, F);
}